// round 12
// baseline (speedup 1.0000x reference)
#include <cuda_runtime.h>
#include <cstdint>

// NodeDropout: out[e] = values[e] if neither endpoint is dropped, else 0.
// edge_index: int32 [2, E], values: f32 [E], nodes_flag: int32 [N]. Output: f32 [E].
//
// R11: R10's full bulk pipeline with the REAL R9/R10 bug fixed: pack kernel
// dropped the last nwords%4 bitmask words (nwords=31250 not divisible by 4),
// leaving 64 nodes unpacked -> deterministic rel_err 3.2e-3. Now ceil-divides
// and bounds-checks the int4 load. Writer-side proxy fence retained.

static constexpr int MAX_WORDS = 32768;
__device__ unsigned int g_bits[MAX_WORDS];

static constexpr int NCONS_W      = 20;                  // consumer warps
static constexpr int THREADS      = (NCONS_W + 2) * 32;  // 704
static constexpr int GPT          = NCONS_W * 32;        // 640 float4-groups / tile
static constexpr int BUF_BYTES    = GPT * 16;            // 10240 B per array per stage
static constexpr int STAGE_BYTES  = 3 * BUF_BYTES;       // src + dst + out
static constexpr int NSTAGES      = 3;
static constexpr int MBAR_OFF     = 0;   // per stage: lf@32s, le@32s+8, of@32s+16, oe@32s+24
static constexpr int BUF_OFF      = 128;
static constexpr int BITS_OFF     = BUF_OFF + NSTAGES * STAGE_BYTES; // 92288

// ---- PTX helpers ----
__device__ __forceinline__ uint32_t smem_u32(const void* p) {
    return (uint32_t)__cvta_generic_to_shared(p);
}
__device__ __forceinline__ void mbar_init(uint32_t a, uint32_t cnt) {
    asm volatile("mbarrier.init.shared.b64 [%0], %1;" :: "r"(a), "r"(cnt) : "memory");
}
__device__ __forceinline__ void mbar_expect_tx(uint32_t a, uint32_t bytes) {
    asm volatile("mbarrier.arrive.expect_tx.shared.b64 _, [%0], %1;" :: "r"(a), "r"(bytes) : "memory");
}
__device__ __forceinline__ void mbar_arrive(uint32_t a) {
    asm volatile("mbarrier.arrive.shared.b64 _, [%0];" :: "r"(a) : "memory");
}
__device__ __forceinline__ void mbar_wait(uint32_t a, uint32_t parity) {
    uint32_t done = 0;
    while (!done) {
        asm volatile(
            "{\n\t.reg .pred p;\n\t"
            "mbarrier.try_wait.parity.shared.b64 p, [%1], %2;\n\t"
            "selp.b32 %0, 1, 0, p;\n\t}"
            : "=r"(done) : "r"(a), "r"(parity) : "memory");
    }
}
__device__ __forceinline__ void bulk_g2s(uint32_t dst, const void* src,
                                         uint32_t bytes, uint32_t mbar) {
    asm volatile(
        "cp.async.bulk.shared::cluster.global.mbarrier::complete_tx::bytes "
        "[%0], [%1], %2, [%3];"
        :: "r"(dst), "l"(src), "r"(bytes), "r"(mbar) : "memory");
}
__device__ __forceinline__ void bulk_s2g(void* dst, uint32_t src, uint32_t bytes) {
    asm volatile(
        "cp.async.bulk.global.shared::cta.bulk_group [%0], [%1], %2;"
        :: "l"(dst), "r"(src), "r"(bytes) : "memory");
}
__device__ __forceinline__ void bulk_commit() {
    asm volatile("cp.async.bulk.commit_group;" ::: "memory");
}
template <int N>
__device__ __forceinline__ void bulk_wait_read() {
    asm volatile("cp.async.bulk.wait_group.read %0;" :: "n"(N) : "memory");
}
__device__ __forceinline__ void fence_async_proxy() {
    asm volatile("fence.proxy.async.shared::cta;" ::: "memory");
}

// ---- Kernel 1: pack int32 flags -> bitmask; 128 flags per warp via int4 ----
__global__ __launch_bounds__(1024)
void pack_flags_kernel(const int4* __restrict__ flag4, int nflag4, int nwords4) {
    int warp = (blockIdx.x * blockDim.x + threadIdx.x) >> 5;
    int lane = threadIdx.x & 31;
    if (warp >= nwords4) return;          // each warp produces up to 4 words
    int fi = warp * 32 + lane;
    int4 f = (fi < nflag4) ? __ldg(&flag4[fi]) : make_int4(0, 0, 0, 0);
    // Node n = warp*128 + 4*lane + c. Word w holds nodes warp*128+32w..+31,
    // contributed by lanes 8w..8w+7 at bits 4*(lane&7)+c.
    unsigned int quad = ((f.x != 0) ? 1u : 0u) | ((f.y != 0) ? 2u : 0u) |
                        ((f.z != 0) ? 4u : 0u) | ((f.w != 0) ? 8u : 0u);
    unsigned int word = quad << (4 * (lane & 7));
    word |= __shfl_xor_sync(0xFFFFFFFFu, word, 1);
    word |= __shfl_xor_sync(0xFFFFFFFFu, word, 2);
    word |= __shfl_xor_sync(0xFFFFFFFFu, word, 4);
    if ((lane & 7) == 0) {
        int w = warp * 4 + (lane >> 3);
        if (w < MAX_WORDS) g_bits[w] = word;
    }
}

// ---- Kernel 2: persistent pipelined main kernel ----
__global__ __launch_bounds__(THREADS, 1)
void node_dropout_kernel(const int4* __restrict__ src4,
                         const int4* __restrict__ dst4,
                         const float4* __restrict__ vals,
                         float4* __restrict__ out,
                         int n4, int ntiles, int nwords) {
    extern __shared__ __align__(16) unsigned char smem_raw[];
    unsigned int* s_bits = (unsigned int*)(smem_raw + BITS_OFF);
    uint32_t mb = smem_u32(smem_raw + MBAR_OFF);
    int tid  = threadIdx.x;
    int warp = tid >> 5;
    int lane = tid & 31;

    for (int w = tid; w < nwords; w += THREADS)
        s_bits[w] = g_bits[w];

    if (tid == 0) {
        for (int s = 0; s < NSTAGES; s++) {
            mbar_init(mb + 32 * s,      1);        // load_full (expect_tx)
            mbar_init(mb + 32 * s + 8,  NCONS_W);  // load_empty
            mbar_init(mb + 32 * s + 16, NCONS_W);  // out_full
            mbar_init(mb + 32 * s + 24, 1);        // out_empty (storer arrives)
        }
    }
    __syncthreads();

    if (warp == NCONS_W) {
        // ---- Load producer (lane 0): keep NSTAGES transfers in flight ----
        if (lane == 0) {
            int stage = 0, phase = 1;   // fresh barrier: parity-1 wait passes now
            for (int t = blockIdx.x; t < ntiles; t += gridDim.x) {
                int g0 = t * GPT;
                uint32_t bytes = (uint32_t)min(GPT, n4 - g0) * 16u;
                uint32_t lf = mb + 32 * stage;
                mbar_wait(lf + 8, phase);          // load_empty
                mbar_expect_tx(lf, bytes * 2u);
                uint32_t base = smem_u32(smem_raw + BUF_OFF + stage * STAGE_BYTES);
                bulk_g2s(base,             src4 + g0, bytes, lf);
                bulk_g2s(base + BUF_BYTES, dst4 + g0, bytes, lf);
                if (++stage == NSTAGES) { stage = 0; phase ^= 1; }
            }
        }
    } else if (warp == NCONS_W + 1) {
        // ---- Storer (lane 0): bulk out bursts, up to 2 in flight ----
        if (lane == 0) {
            int stage = 0, phase = 0, prev_stage = -1;
            for (int t = blockIdx.x; t < ntiles; t += gridDim.x) {
                int g0 = t * GPT;
                uint32_t bytes = (uint32_t)min(GPT, n4 - g0) * 16u;
                mbar_wait(mb + 32 * stage + 16, phase);  // out_full (acquire)
                fence_async_proxy();
                uint32_t ob = smem_u32(smem_raw + BUF_OFF + stage * STAGE_BYTES
                                       + 2 * BUF_BYTES);
                bulk_s2g(out + g0, ob, bytes);
                bulk_commit();
                if (prev_stage >= 0) {
                    bulk_wait_read<1>();                     // oldest read done
                    mbar_arrive(mb + 32 * prev_stage + 24);  // out_empty
                }
                prev_stage = stage;
                if (++stage == NSTAGES) { stage = 0; phase ^= 1; }
            }
            if (prev_stage >= 0) {
                bulk_wait_read<0>();
                mbar_arrive(mb + 32 * prev_stage + 24);
            }
        }
    } else {
        // ---- Consumer warps 0..NCONS_W-1 ----
        int stage = 0, lphase = 0, ephase = 1;
        int g = tid;                 // 0..GPT-1
        int gs = gridDim.x;

        int t = blockIdx.x;
        float4 v_cur = make_float4(0.f, 0.f, 0.f, 0.f);
        if (t < ntiles && g < n4 - t * GPT) v_cur = __ldg(&vals[t * GPT + g]);

        for (; t < ntiles; t += gs) {
            int g0 = t * GPT;
            int cnt = min(GPT, n4 - g0);
            bool act = (g < cnt);

            int tn = t + gs;
            float4 v_next = make_float4(0.f, 0.f, 0.f, 0.f);
            if (tn < ntiles && g < n4 - tn * GPT) v_next = __ldg(&vals[tn * GPT + g]);

            uint32_t sb32 = mb + 32 * stage;
            mbar_wait(sb32, lphase);             // load_full (acquire)

            unsigned char* sbuf = smem_raw + BUF_OFF + stage * STAGE_BYTES;
            float4 o = make_float4(0.f, 0.f, 0.f, 0.f);
            if (act) {
                int4 s = ((const int4*)(sbuf))[g];
                int4 d = ((const int4*)(sbuf + BUF_BYTES))[g];
                unsigned int b0 = (s_bits[((unsigned)s.x) >> 5] >> (s.x & 31)) |
                                  (s_bits[((unsigned)d.x) >> 5] >> (d.x & 31));
                unsigned int b1 = (s_bits[((unsigned)s.y) >> 5] >> (s.y & 31)) |
                                  (s_bits[((unsigned)d.y) >> 5] >> (d.y & 31));
                unsigned int b2 = (s_bits[((unsigned)s.z) >> 5] >> (s.z & 31)) |
                                  (s_bits[((unsigned)d.z) >> 5] >> (d.z & 31));
                unsigned int b3 = (s_bits[((unsigned)s.w) >> 5] >> (s.w & 31)) |
                                  (s_bits[((unsigned)d.w) >> 5] >> (d.w & 31));
                o.x = (b0 & 1u) ? 0.0f : v_cur.x;
                o.y = (b1 & 1u) ? 0.0f : v_cur.y;
                o.z = (b2 & 1u) ? 0.0f : v_cur.z;
                o.w = (b3 & 1u) ? 0.0f : v_cur.w;
            }
            mbar_wait(sb32 + 24, ephase);        // out_empty (buffer reusable)
            if (act) ((float4*)(sbuf + 2 * BUF_BYTES))[g] = o;
            // Writer-side proxy fence before signaling the storer.
            fence_async_proxy();
            __syncwarp();
            if (lane == 0) {
                mbar_arrive(sb32 + 16);          // out_full
                mbar_arrive(sb32 + 8);           // load_empty
            }
            v_cur = v_next;
            if (++stage == NSTAGES) { stage = 0; lphase ^= 1; ephase ^= 1; }
        }
    }
}

extern "C" void kernel_launch(void* const* d_in, const int* in_sizes, int n_in,
                              void* d_out, int out_size) {
    // metadata order: edge_index [2, E] int32, values [E] f32, nodes_flag [N] int32
    const int* edge_index = (const int*)d_in[0];
    const float* values = (const float*)d_in[1];
    const int* nodes_flag = (const int*)d_in[2];
    float* out = (float*)d_out;

    int e = in_sizes[1];
    int nflags = in_sizes[2];              // 1,000,000 (divisible by 4)
    int n4 = e / 4;
    int nwords = (nflags + 31) / 32;       // 31250
    int ntiles = (n4 + GPT - 1) / GPT;
    size_t smem_bytes = (size_t)BITS_OFF + (size_t)nwords * 4;

    const int* src = edge_index;
    const int* dst = edge_index + e;

    int nflag4 = nflags / 4;               // 250000 int4 loads
    int nwords4 = (nwords + 3) / 4;        // 7813  (FIX: ceil, was floor)
    int pack_blocks = (nwords4 * 32 + 1023) / 1024;
    pack_flags_kernel<<<pack_blocks, 1024>>>((const int4*)nodes_flag, nflag4, nwords4);

    int num_sms = 148;
    cudaDeviceGetAttribute(&num_sms, cudaDevAttrMultiProcessorCount, 0);
    cudaFuncSetAttribute(node_dropout_kernel,
                         cudaFuncAttributeMaxDynamicSharedMemorySize,
                         (int)smem_bytes);

    node_dropout_kernel<<<num_sms, THREADS, smem_bytes>>>(
        (const int4*)src, (const int4*)dst, (const float4*)values,
        (float4*)out, n4, ntiles, nwords);
}

// round 14
// speedup vs baseline: 1.0474x; 1.0474x over previous
#include <cuda_runtime.h>
#include <cstdint>

// NodeDropout: out[e] = values[e] if neither endpoint is dropped, else 0.
// edge_index: int32 [2, E], values: f32 [E], nodes_flag: int32 [N]. Output: f32 [E].
//
// R13 = R12 resubmitted (R13 bench was an infra container failure, no kernel
// signal). Structure: bulk (TMA-path) loads for src/dst with a 3-stage
// mbarrier pipeline; values prefetched into registers one tile ahead; output
// via plain consumer STG.128 (R11 proved bulk stores regress). GPT=1024
// (2 float4-groups/consumer thread) to amortize per-tile sync cost; producer
// starts streaming BEFORE the 125 KB bitmask staging completes (consumer-only
// named barrier) to kill the kernel-start DRAM bubble.

static constexpr int MAX_WORDS = 32768;
__device__ unsigned int g_bits[MAX_WORDS];

static constexpr int NCONS_W     = 16;                    // consumer warps
static constexpr int CONS_T      = NCONS_W * 32;          // 512 consumer threads
static constexpr int THREADS     = CONS_T + 32;           // +1 producer warp = 544
static constexpr int GPG         = 2;                     // float4-groups per thread
static constexpr int GPT         = CONS_T * GPG;          // 1024 groups per tile
static constexpr int BUF_BYTES   = GPT * 16;              // 16384 per array per stage
static constexpr int STAGE_BYTES = 2 * BUF_BYTES;         // src + dst
static constexpr int NSTAGES     = 3;
static constexpr int MBAR_OFF    = 0;                     // full@16s, empty@16s+8
static constexpr int BUF_OFF     = 128;
static constexpr int BITS_OFF    = BUF_OFF + NSTAGES * STAGE_BYTES; // 98432

// ---- PTX helpers ----
__device__ __forceinline__ uint32_t smem_u32(const void* p) {
    return (uint32_t)__cvta_generic_to_shared(p);
}
__device__ __forceinline__ void mbar_init(uint32_t a, uint32_t cnt) {
    asm volatile("mbarrier.init.shared.b64 [%0], %1;" :: "r"(a), "r"(cnt) : "memory");
}
__device__ __forceinline__ void mbar_expect_tx(uint32_t a, uint32_t bytes) {
    asm volatile("mbarrier.arrive.expect_tx.shared.b64 _, [%0], %1;" :: "r"(a), "r"(bytes) : "memory");
}
__device__ __forceinline__ void mbar_arrive(uint32_t a) {
    asm volatile("mbarrier.arrive.shared.b64 _, [%0];" :: "r"(a) : "memory");
}
__device__ __forceinline__ void mbar_wait(uint32_t a, uint32_t parity) {
    uint32_t done = 0;
    while (!done) {
        asm volatile(
            "{\n\t.reg .pred p;\n\t"
            "mbarrier.try_wait.parity.shared.b64 p, [%1], %2;\n\t"
            "selp.b32 %0, 1, 0, p;\n\t}"
            : "=r"(done) : "r"(a), "r"(parity) : "memory");
    }
}
__device__ __forceinline__ void bulk_g2s(uint32_t dst, const void* src,
                                         uint32_t bytes, uint32_t mbar) {
    asm volatile(
        "cp.async.bulk.shared::cluster.global.mbarrier::complete_tx::bytes "
        "[%0], [%1], %2, [%3];"
        :: "r"(dst), "l"(src), "r"(bytes), "r"(mbar) : "memory");
}

// ---- Kernel 1: pack int32 flags -> bitmask; 128 flags per warp via int4 ----
__global__ __launch_bounds__(1024)
void pack_flags_kernel(const int4* __restrict__ flag4, int nflag4, int nwords4) {
    int warp = (blockIdx.x * blockDim.x + threadIdx.x) >> 5;
    int lane = threadIdx.x & 31;
    if (warp >= nwords4) return;
    int fi = warp * 32 + lane;
    int4 f = (fi < nflag4) ? __ldg(&flag4[fi]) : make_int4(0, 0, 0, 0);
    unsigned int quad = ((f.x != 0) ? 1u : 0u) | ((f.y != 0) ? 2u : 0u) |
                        ((f.z != 0) ? 4u : 0u) | ((f.w != 0) ? 8u : 0u);
    unsigned int word = quad << (4 * (lane & 7));
    word |= __shfl_xor_sync(0xFFFFFFFFu, word, 1);
    word |= __shfl_xor_sync(0xFFFFFFFFu, word, 2);
    word |= __shfl_xor_sync(0xFFFFFFFFu, word, 4);
    if ((lane & 7) == 0) {
        int w = warp * 4 + (lane >> 3);
        if (w < MAX_WORDS) g_bits[w] = word;
    }
}

__device__ __forceinline__ float4 mask_one(const unsigned int* s_bits,
                                           int4 s, int4 d, float4 v) {
    unsigned int b0 = (s_bits[((unsigned)s.x) >> 5] >> (s.x & 31)) |
                      (s_bits[((unsigned)d.x) >> 5] >> (d.x & 31));
    unsigned int b1 = (s_bits[((unsigned)s.y) >> 5] >> (s.y & 31)) |
                      (s_bits[((unsigned)d.y) >> 5] >> (d.y & 31));
    unsigned int b2 = (s_bits[((unsigned)s.z) >> 5] >> (s.z & 31)) |
                      (s_bits[((unsigned)d.z) >> 5] >> (d.z & 31));
    unsigned int b3 = (s_bits[((unsigned)s.w) >> 5] >> (s.w & 31)) |
                      (s_bits[((unsigned)d.w) >> 5] >> (d.w & 31));
    float4 o;
    o.x = (b0 & 1u) ? 0.0f : v.x;
    o.y = (b1 & 1u) ? 0.0f : v.y;
    o.z = (b2 & 1u) ? 0.0f : v.z;
    o.w = (b3 & 1u) ? 0.0f : v.w;
    return o;
}

// ---- Kernel 2: persistent pipelined main kernel ----
__global__ __launch_bounds__(THREADS, 1)
void node_dropout_kernel(const int4* __restrict__ src4,
                         const int4* __restrict__ dst4,
                         const float4* __restrict__ vals,
                         float4* __restrict__ out,
                         int n4, int ntiles, int nwords) {
    extern __shared__ __align__(16) unsigned char smem_raw[];
    unsigned int* s_bits = (unsigned int*)(smem_raw + BITS_OFF);
    uint32_t mb = smem_u32(smem_raw + MBAR_OFF);
    int tid  = threadIdx.x;
    int warp = tid >> 5;
    int lane = tid & 31;

    // Barriers first so the producer can start streaming immediately.
    if (tid == 0) {
        for (int s = 0; s < NSTAGES; s++) {
            mbar_init(mb + 16 * s,     1);        // full (expect_tx)
            mbar_init(mb + 16 * s + 8, NCONS_W);  // empty
        }
    }
    __syncthreads();

    if (warp == NCONS_W) {
        // ---- Producer (lane 0): starts before bitmask staging finishes ----
        if (lane == 0) {
            int stage = 0, phase = 1;   // fresh barrier: parity-1 waits pass
            for (int t = blockIdx.x; t < ntiles; t += gridDim.x) {
                int g0 = t * GPT;
                uint32_t bytes = (uint32_t)min(GPT, n4 - g0) * 16u;
                uint32_t full = mb + 16 * stage;
                mbar_wait(full + 8, phase);       // empty
                mbar_expect_tx(full, bytes * 2u);
                uint32_t base = smem_u32(smem_raw + BUF_OFF + stage * STAGE_BYTES);
                bulk_g2s(base,             src4 + g0, bytes, full);
                bulk_g2s(base + BUF_BYTES, dst4 + g0, bytes, full);
                if (++stage == NSTAGES) { stage = 0; phase ^= 1; }
            }
        }
    } else {
        // ---- Consumers: stage bitmask, then pipeline loop ----
        for (int w = tid; w < nwords; w += CONS_T)
            s_bits[w] = g_bits[w];
        // Consumer-only barrier (producer excluded): all s_bits visible.
        asm volatile("bar.sync 1, %0;" :: "n"(CONS_T) : "memory");

        int stage = 0, phase = 0;
        int g0l = tid;              // first group handled by this thread
        int g1l = tid + CONS_T;     // second group
        int gs = gridDim.x;

        int t = blockIdx.x;
        float4 v_cur0 = make_float4(0.f, 0.f, 0.f, 0.f);
        float4 v_cur1 = make_float4(0.f, 0.f, 0.f, 0.f);
        if (t < ntiles) {
            int b = t * GPT;
            if (g0l < n4 - b) v_cur0 = __ldg(&vals[b + g0l]);
            if (g1l < n4 - b) v_cur1 = __ldg(&vals[b + g1l]);
        }

        for (; t < ntiles; t += gs) {
            int g0 = t * GPT;
            int cnt = min(GPT, n4 - g0);

            // Prefetch next tile's values (full iteration to land).
            int tn = t + gs;
            float4 v_nx0 = make_float4(0.f, 0.f, 0.f, 0.f);
            float4 v_nx1 = make_float4(0.f, 0.f, 0.f, 0.f);
            if (tn < ntiles) {
                int bn = tn * GPT;
                if (g0l < n4 - bn) v_nx0 = __ldg(&vals[bn + g0l]);
                if (g1l < n4 - bn) v_nx1 = __ldg(&vals[bn + g1l]);
            }

            uint32_t full = mb + 16 * stage;
            mbar_wait(full, phase);              // acquire

            const unsigned char* sb = smem_raw + BUF_OFF + stage * STAGE_BYTES;
            const int4* ssrc = (const int4*)sb;
            const int4* sdst = (const int4*)(sb + BUF_BYTES);

            if (g0l < cnt) {
                int4 s = ssrc[g0l];
                int4 d = sdst[g0l];
                out[g0 + g0l] = mask_one(s_bits, s, d, v_cur0);
            }
            if (g1l < cnt) {
                int4 s = ssrc[g1l];
                int4 d = sdst[g1l];
                out[g0 + g1l] = mask_one(s_bits, s, d, v_cur1);
            }
            __syncwarp();
            if (lane == 0) mbar_arrive(full + 8);  // empty
            v_cur0 = v_nx0;
            v_cur1 = v_nx1;
            if (++stage == NSTAGES) { stage = 0; phase ^= 1; }
        }
    }
}

extern "C" void kernel_launch(void* const* d_in, const int* in_sizes, int n_in,
                              void* d_out, int out_size) {
    // metadata order: edge_index [2, E] int32, values [E] f32, nodes_flag [N] int32
    const int* edge_index = (const int*)d_in[0];
    const float* values = (const float*)d_in[1];
    const int* nodes_flag = (const int*)d_in[2];
    float* out = (float*)d_out;

    int e = in_sizes[1];
    int nflags = in_sizes[2];              // 1,000,000
    int n4 = e / 4;                        // 5,000,000
    int nwords = (nflags + 31) / 32;       // 31250
    int ntiles = (n4 + GPT - 1) / GPT;
    size_t smem_bytes = (size_t)BITS_OFF + (size_t)nwords * 4;  // 223432

    const int* src = edge_index;
    const int* dst = edge_index + e;

    int nflag4 = nflags / 4;
    int nwords4 = (nwords + 3) / 4;        // ceil — covers the tail words
    int pack_blocks = (nwords4 * 32 + 1023) / 1024;
    pack_flags_kernel<<<pack_blocks, 1024>>>((const int4*)nodes_flag, nflag4, nwords4);

    int num_sms = 148;
    cudaDeviceGetAttribute(&num_sms, cudaDevAttrMultiProcessorCount, 0);
    cudaFuncSetAttribute(node_dropout_kernel,
                         cudaFuncAttributeMaxDynamicSharedMemorySize,
                         (int)smem_bytes);

    node_dropout_kernel<<<num_sms, THREADS, smem_bytes>>>(
        (const int4*)src, (const int4*)dst, (const float4*)values,
        (float4*)out, n4, ntiles, nwords);
}